// round 15
// baseline (speedup 1.0000x reference)
#include <cuda_runtime.h>
#include <math.h>

#define EPSF 1e-8f
#define NHALF_LOG2E (-0.72134752044448170f)   // -0.5 * log2(e)

constexpr int Bn  = 4096;
constexpr int Ln  = 1024;
constexpr int Kc  = 4;
constexpr int NIT = 5;
constexpr int TPB = 128;        // 4 warps = 4 rows per CTA
constexpr int RPB = 4;          // one warp per row
constexpr int NP  = 16;         // packed pairs per lane (32 positions)

using u64 = unsigned long long;

__device__ __forceinline__ float ex2f(float x){ float r; asm("ex2.approx.ftz.f32 %0, %1;":"=f"(r):"f"(x)); return r; }
__device__ __forceinline__ float rcpf(float x){ float r; asm("rcp.approx.ftz.f32 %0, %1;":"=f"(r):"f"(x)); return r; }

__device__ __forceinline__ u64 pk2(float lo, float hi){ u64 r; asm("mov.b64 %0, {%1, %2};":"=l"(r):"f"(lo),"f"(hi)); return r; }
__device__ __forceinline__ void up2(u64 v, float& lo, float& hi){ asm("mov.b64 {%0, %1}, %2;":"=f"(lo),"=f"(hi):"l"(v)); }
__device__ __forceinline__ u64 fma2(u64 a, u64 b, u64 c){ u64 d; asm("fma.rn.f32x2 %0, %1, %2, %3;":"=l"(d):"l"(a),"l"(b),"l"(c)); return d; }
__device__ __forceinline__ u64 add2(u64 a, u64 b){ u64 d; asm("add.rn.f32x2 %0, %1, %2;":"=l"(d):"l"(a),"l"(b)); return d; }
__device__ __forceinline__ u64 mul2(u64 a, u64 b){ u64 d; asm("mul.rn.f32x2 %0, %1, %2;":"=l"(d):"l"(a),"l"(b)); return d; }

// sm_100a: no redux.f32 — classic butterfly
__device__ __forceinline__ float warp_sum(float v){
#pragma unroll
    for (int o = 16; o; o >>= 1) v += __shfl_xor_sync(0xffffffffu, v, o);
    return v;
}
__device__ __forceinline__ float rsum2(u64 v){
    float a, b; up2(v, a, b);
    return warp_sum(a + b);
}

__device__ __forceinline__ void make_deltas(float qa, float qb, float qc,
                                            u64* dqa, u64* dqb, u64* dqc) {
    const unsigned F = 0xffffffffu;
    float a0 = __shfl_sync(F, qa, 0), a1 = __shfl_sync(F, qa, 1),
          a2 = __shfl_sync(F, qa, 2), a3 = __shfl_sync(F, qa, 3);
    float b0 = __shfl_sync(F, qb, 0), b1 = __shfl_sync(F, qb, 1),
          b2 = __shfl_sync(F, qb, 2), b3 = __shfl_sync(F, qb, 3);
    float c0 = __shfl_sync(F, qc, 0), c1 = __shfl_sync(F, qc, 1),
          c2 = __shfl_sync(F, qc, 2), c3 = __shfl_sync(F, qc, 3);
    float d;
    d = a1 - a0; dqa[0] = pk2(d, d);
    d = a2 - a0; dqa[1] = pk2(d, d);
    d = a3 - a0; dqa[2] = pk2(d, d);
    d = b1 - b0; dqb[0] = pk2(d, d);
    d = b2 - b0; dqb[1] = pk2(d, d);
    d = b3 - b0; dqb[2] = pk2(d, d);
    d = c1 - c0; dqc[0] = pk2(d, d);
    d = c2 - c0; dqc[1] = pk2(d, d);
    d = c3 - c0; dqc[2] = pk2(d, d);
}

__global__ __launch_bounds__(TPB, 5) void em_kernel(
    const float* __restrict__ windows,        // [B, L]
    const float* __restrict__ noise,          // [B, K]
    const float* __restrict__ init_centers,   // [K]
    const float* __restrict__ init_scales,    // [K]
    const float* __restrict__ init_weights,   // [K]
    const float* __restrict__ prior_p_param,  // [1]
    const float* __restrict__ mixw,           // [1, L]
    const float* __restrict__ blend,          // [1]
    float* __restrict__ out)                  // g [B,L,K] ++ p ++ a ++ b
{
    __shared__ u64 wsh[2 * NP][32];           // exp(mixw) pairs; group = 2j+h

    const int lane = threadIdx.x & 31;
    const int wid  = threadIdx.x >> 5;
    const int row  = blockIdx.x * RPB + wid;

    // ---- stage per-position weights (same for every row) ----
#pragma unroll
    for (int r = 0; r < 2; r++) {
        int idx = threadIdx.x + r * TPB;      // float4 index 0..255
        float4 m = reinterpret_cast<const float4*>(mixw)[idx];
        int hj = idx >> 5, ln = idx & 31;
        wsh[2 * hj][ln]     = pk2(__expf(m.x), __expf(m.y));
        wsh[2 * hj + 1][ln] = pk2(__expf(m.z), __expf(m.w));
    }

    // ---- load full row into registers; mean ----
    const float4* __restrict__ xv =
        reinterpret_cast<const float4*>(windows + (size_t)row * Ln);
    u64 tp[NP];
    float s = 0.f;
#pragma unroll
    for (int j = 0; j < 8; j++) {
        float4 a = xv[lane + 32 * j];
        tp[2 * j]     = pk2(a.x, a.y);
        tp[2 * j + 1] = pk2(a.z, a.w);
        s += (a.x + a.y) + (a.z + a.w);
    }
    const float mean = warp_sum(s) * (1.0f / Ln);

    __syncthreads();                          // wsh staging done (only CTA-wide sync)

    // ---- center; var + constant W-moments in one pass ----
    const u64 nm2 = pk2(-mean, -mean);
    u64 ssp = 0ull, W0p = 0ull, W1p = 0ull, W2p = 0ull;
#pragma unroll
    for (int p = 0; p < NP; p++) {
        tp[p] = add2(tp[p], nm2);
        ssp   = fma2(tp[p], tp[p], ssp);
        u64 w2 = wsh[p][lane];
        W0p = add2(W0p, w2);
        u64 wt = mul2(w2, tp[p]);
        W1p = add2(W1p, wt);
        W2p = fma2(wt, tp[p], W2p);
    }
    const float var = rsum2(ssp) * (1.0f / (Ln - 1));
    const float W0  = rsum2(W0p);
    const float W1  = rsum2(W1p);
    const float W2  = rsum2(W2p);

    const float prior_var = var;
    const float stdv      = sqrtf(var);
    const float prior_p   = rcpf(1.f + __expf(-prior_p_param[0]));
    const float blender   = rcpf(1.f + __expf(-blend[0]));
    const float omb       = 1.f - blender;

    // ---- initial params: lane handles k = lane&3 ----
    const int k = lane & 3;
    float al_ = (init_centers[k] + noise[(size_t)row * Kc + k] * 0.01f) * stdv;
    float bb  = fabsf(init_scales[k]) * stdv;
    float pkn = init_weights[k];
    float ib  = rcpf(bb + EPSF);
    float qa  = NHALF_LOG2E * ib * ib;
    float qb  = -2.f * qa * al_;
    float qc  = fmaf(qa * al_, al_, __log2f((pkn + EPSF) * ib));

    u64 dqa[3], dqb[3], dqc[3];
    make_deltas(qa, qb, qc, dqa, dqb, dqc);

    const u64 one2 = pk2(1.f, 1.f);
    float4* __restrict__ gout = reinterpret_cast<float4*>(out) + (size_t)row * Ln;

    // ---- EM iterations: warp fully independent, no barriers ----
#pragma unroll 1
    for (int it = 0; it < NIT; ++it) {
        const bool last = (it == NIT - 1);
        u64 A0[3] = {0ull, 0ull, 0ull};
        u64 A1[3] = {0ull, 0ull, 0ull};
        u64 A2[3] = {0ull, 0ull, 0ull};

#pragma unroll
        for (int p = 0; p < NP; p++) {
            const u64 tpp = tp[p];
            u64 d1 = fma2(fma2(dqa[0], tpp, dqb[0]), tpp, dqc[0]);
            u64 d2 = fma2(fma2(dqa[1], tpp, dqb[1]), tpp, dqc[1]);
            u64 d3 = fma2(fma2(dqa[2], tpp, dqb[2]), tpp, dqc[2]);
            float d1l, d1h, d2l, d2h, d3l, d3h;
            up2(d1, d1l, d1h); up2(d2, d2l, d2h); up2(d3, d3l, d3h);
            u64 e1 = pk2(ex2f(d1l), ex2f(d1h));
            u64 e2 = pk2(ex2f(d2l), ex2f(d2h));
            u64 e3 = pk2(ex2f(d3l), ex2f(d3h));
            u64 sm2 = add2(add2(e1, e2), add2(e3, one2));
            float sl, sh; up2(sm2, sl, sh);
            // paired reciprocal: one MUFU for both halves
            float rr = rcpf(sl * sh);
            u64 rs2 = pk2(rr * sh, rr * sl);
            u64 ws2 = mul2(wsh[p][lane], rs2);

            if (last) {
                u64 g1 = mul2(e1, rs2), g2 = mul2(e2, rs2), g3 = mul2(e3, rs2);
                float rl, rh, g1l, g1h, g2l, g2h, g3l, g3h;
                up2(rs2, rl, rh); up2(g1, g1l, g1h); up2(g2, g2l, g2h); up2(g3, g3l, g3h);
                const int j = p >> 1, c = p & 1;
                const int pos = (lane + 32 * j) * 4 + 2 * c;
                gout[pos]     = make_float4(rl, g1l, g2l, g3l);
                gout[pos + 1] = make_float4(rh, g1h, g2h, g3h);
            }

            u64 f1 = mul2(e1, ws2);
            u64 f2 = mul2(e2, ws2);
            u64 tq = mul2(tpp, tpp);
            A0[0] = add2(A0[0], ws2);      A0[1] = add2(A0[1], f1);      A0[2] = add2(A0[2], f2);
            A1[0] = fma2(ws2, tpp, A1[0]); A1[1] = fma2(f1, tpp, A1[1]); A1[2] = fma2(f2, tpp, A1[2]);
            A2[0] = fma2(ws2, tq, A2[0]);  A2[1] = fma2(f1, tq, A2[1]);  A2[2] = fma2(f2, tq, A2[2]);
        }

        // ---- intra-warp reduce 9 moments; k=3 via conserved totals ----
        float S00 = rsum2(A0[0]), S01 = rsum2(A0[1]), S02 = rsum2(A0[2]);
        float S10 = rsum2(A1[0]), S11 = rsum2(A1[1]), S12 = rsum2(A1[2]);
        float S20 = rsum2(A2[0]), S21 = rsum2(A2[1]), S22 = rsum2(A2[2]);

        float S0k = (k == 0) ? S00 : (k == 1) ? S01 : (k == 2) ? S02 : (W0 - S00 - S01 - S02);
        float S1k = (k == 0) ? S10 : (k == 1) ? S11 : (k == 2) ? S12 : (W1 - S10 - S11 - S12);
        float S2k = (k == 0) ? S20 : (k == 1) ? S21 : (k == 2) ? S22 : (W2 - S20 - S21 - S22);

        // ---- m-step: lane computes its k ----
        float sg = fmaxf(S0k, EPSF);
        float pv = sg + prior_p;
        float psum = pv;
        psum += __shfl_xor_sync(0xffffffffu, psum, 1);
        psum += __shfl_xor_sync(0xffffffffu, psum, 2);
        pkn = pv * rcpf(psum);
        float rsg = rcpf(sg);
        al_ = blender * S1k * rsg;                                  // a - mean
        float dv = fmaf(al_, fmaf(al_, S0k, -2.f * S1k), S2k) * rsg;
        bb = sqrtf(fmaf(dv, blender, fmaf(prior_var, omb, EPSF)));
        ib = rcpf(bb + EPSF);
        qa = NHALF_LOG2E * ib * ib;
        qb = -2.f * qa * al_;
        qc = fmaf(qa * al_, al_, __log2f((pkn + EPSF) * ib));
        make_deltas(qa, qb, qc, dqa, dqb, dqc);
    }

    // ---- tail outputs: p, a, b (lane < 4 holds k = lane) ----
    if (lane < Kc) {
        size_t base = (size_t)Bn * Ln * Kc;
        out[base + (size_t)row * Kc + lane]                       = pkn;
        out[base + (size_t)Bn * Kc + (size_t)row * Kc + lane]     = al_ + mean;
        out[base + 2 * (size_t)Bn * Kc + (size_t)row * Kc + lane] = bb;
    }
}

extern "C" void kernel_launch(void* const* d_in, const int* in_sizes, int n_in,
                              void* d_out, int out_size) {
    (void)in_sizes; (void)n_in; (void)out_size;
    em_kernel<<<Bn / RPB, TPB>>>((const float*)d_in[0], (const float*)d_in[1],
                                 (const float*)d_in[2], (const float*)d_in[3],
                                 (const float*)d_in[4], (const float*)d_in[5],
                                 (const float*)d_in[6], (const float*)d_in[7],
                                 (float*)d_out);
}

// round 17
// speedup vs baseline: 1.3876x; 1.3876x over previous
#include <cuda_runtime.h>
#include <math.h>

#define EPSF 1e-8f
#define NHALF_LOG2E (-0.72134752044448170f)   // -0.5 * log2(e)

constexpr int Bn  = 4096;
constexpr int Ln  = 1024;
constexpr int Kc  = 4;
constexpr int NIT = 5;
constexpr int TPB = 128;        // 4 warps = 4 rows per CTA
constexpr int RPB = 4;          // one warp per row
constexpr int NP  = 16;         // packed pairs per lane (32 positions)

using u64 = unsigned long long;

__device__ __forceinline__ float ex2f(float x){ float r; asm("ex2.approx.ftz.f32 %0, %1;":"=f"(r):"f"(x)); return r; }
__device__ __forceinline__ float rcpf(float x){ float r; asm("rcp.approx.ftz.f32 %0, %1;":"=f"(r):"f"(x)); return r; }

__device__ __forceinline__ u64 pk2(float lo, float hi){ u64 r; asm("mov.b64 %0, {%1, %2};":"=l"(r):"f"(lo),"f"(hi)); return r; }
__device__ __forceinline__ void up2(u64 v, float& lo, float& hi){ asm("mov.b64 {%0, %1}, %2;":"=f"(lo),"=f"(hi):"l"(v)); }
__device__ __forceinline__ u64 fma2(u64 a, u64 b, u64 c){ u64 d; asm("fma.rn.f32x2 %0, %1, %2, %3;":"=l"(d):"l"(a),"l"(b),"l"(c)); return d; }
__device__ __forceinline__ u64 add2(u64 a, u64 b){ u64 d; asm("add.rn.f32x2 %0, %1, %2;":"=l"(d):"l"(a),"l"(b)); return d; }
__device__ __forceinline__ u64 mul2(u64 a, u64 b){ u64 d; asm("mul.rn.f32x2 %0, %1, %2;":"=l"(d):"l"(a),"l"(b)); return d; }

// sm_100a: no redux.f32 — classic butterfly
__device__ __forceinline__ float warp_sum(float v){
#pragma unroll
    for (int o = 16; o; o >>= 1) v += __shfl_xor_sync(0xffffffffu, v, o);
    return v;
}
__device__ __forceinline__ float rsum2(u64 v){
    float a, b; up2(v, a, b);
    return warp_sum(a + b);
}

__device__ __forceinline__ void make_deltas(float qa, float qb, float qc,
                                            u64* dqa, u64* dqb, u64* dqc) {
    const unsigned F = 0xffffffffu;
    float a0 = __shfl_sync(F, qa, 0), a1 = __shfl_sync(F, qa, 1),
          a2 = __shfl_sync(F, qa, 2), a3 = __shfl_sync(F, qa, 3);
    float b0 = __shfl_sync(F, qb, 0), b1 = __shfl_sync(F, qb, 1),
          b2 = __shfl_sync(F, qb, 2), b3 = __shfl_sync(F, qb, 3);
    float c0 = __shfl_sync(F, qc, 0), c1 = __shfl_sync(F, qc, 1),
          c2 = __shfl_sync(F, qc, 2), c3 = __shfl_sync(F, qc, 3);
    float d;
    d = a1 - a0; dqa[0] = pk2(d, d);
    d = a2 - a0; dqa[1] = pk2(d, d);
    d = a3 - a0; dqa[2] = pk2(d, d);
    d = b1 - b0; dqb[0] = pk2(d, d);
    d = b2 - b0; dqb[1] = pk2(d, d);
    d = b3 - b0; dqb[2] = pk2(d, d);
    d = c1 - c0; dqc[0] = pk2(d, d);
    d = c2 - c0; dqc[1] = pk2(d, d);
    d = c3 - c0; dqc[2] = pk2(d, d);
}

__global__ __launch_bounds__(TPB, 5) void em_kernel(
    const float* __restrict__ windows,        // [B, L]
    const float* __restrict__ noise,          // [B, K]
    const float* __restrict__ init_centers,   // [K]
    const float* __restrict__ init_scales,    // [K]
    const float* __restrict__ init_weights,   // [K]
    const float* __restrict__ prior_p_param,  // [1]
    const float* __restrict__ mixw,           // [1, L]
    const float* __restrict__ blend,          // [1]
    float* __restrict__ out)                  // g [B,L,K] ++ p ++ a ++ b
{
    __shared__ u64 wsh[2 * NP][32];           // exp(mixw) pairs; group = 2j+h

    const int lane = threadIdx.x & 31;
    const int wid  = threadIdx.x >> 5;
    const int row  = blockIdx.x * RPB + wid;

    // ---- stage per-position weights (same for every row) ----
#pragma unroll
    for (int r = 0; r < 2; r++) {
        int idx = threadIdx.x + r * TPB;      // float4 index 0..255
        float4 m = reinterpret_cast<const float4*>(mixw)[idx];
        int hj = idx >> 5, ln = idx & 31;
        wsh[2 * hj][ln]     = pk2(__expf(m.x), __expf(m.y));
        wsh[2 * hj + 1][ln] = pk2(__expf(m.z), __expf(m.w));
    }

    // ---- load full row into registers; mean ----
    const float4* __restrict__ xv =
        reinterpret_cast<const float4*>(windows + (size_t)row * Ln);
    u64 tp[NP];
    float s = 0.f;
#pragma unroll
    for (int j = 0; j < 8; j++) {
        float4 a = xv[lane + 32 * j];
        tp[2 * j]     = pk2(a.x, a.y);
        tp[2 * j + 1] = pk2(a.z, a.w);
        s += (a.x + a.y) + (a.z + a.w);
    }
    const float mean = warp_sum(s) * (1.0f / Ln);

    __syncthreads();                          // wsh staging done (only CTA-wide sync)

    // ---- center; var + constant W-moments in one pass ----
    const u64 nm2 = pk2(-mean, -mean);
    u64 ssp = 0ull, W0p = 0ull, W1p = 0ull, W2p = 0ull;
#pragma unroll
    for (int p = 0; p < NP; p++) {
        tp[p] = add2(tp[p], nm2);
        ssp   = fma2(tp[p], tp[p], ssp);
        u64 w2 = wsh[p][lane];
        W0p = add2(W0p, w2);
        u64 wt = mul2(w2, tp[p]);
        W1p = add2(W1p, wt);
        W2p = fma2(wt, tp[p], W2p);
    }
    const float var = rsum2(ssp) * (1.0f / (Ln - 1));
    const float W0  = rsum2(W0p);
    const float W1  = rsum2(W1p);
    const float W2  = rsum2(W2p);

    const float prior_var = var;
    const float stdv      = sqrtf(var);
    const float prior_p   = rcpf(1.f + __expf(-prior_p_param[0]));
    const float blender   = rcpf(1.f + __expf(-blend[0]));
    const float omb       = 1.f - blender;

    // ---- initial params: lane handles k = lane&3 ----
    const int k = lane & 3;
    float al_ = (init_centers[k] + noise[(size_t)row * Kc + k] * 0.01f) * stdv;
    float bb  = fabsf(init_scales[k]) * stdv;
    float pkn = init_weights[k];
    float ib  = rcpf(bb + EPSF);
    float qa  = NHALF_LOG2E * ib * ib;
    float qb  = -2.f * qa * al_;
    float qc  = fmaf(qa * al_, al_, __log2f((pkn + EPSF) * ib));

    u64 dqa[3], dqb[3], dqc[3];
    make_deltas(qa, qb, qc, dqa, dqb, dqc);

    const u64 one2 = pk2(1.f, 1.f);
    float4* __restrict__ gout = reinterpret_cast<float4*>(out) + (size_t)row * Ln;

    // ---- EM iterations: warp fully independent, no barriers ----
#pragma unroll 1
    for (int it = 0; it < NIT; ++it) {
        const bool last = (it == NIT - 1);
        u64 A0[3] = {0ull, 0ull, 0ull};
        u64 A1[3] = {0ull, 0ull, 0ull};
        u64 A2[3] = {0ull, 0ull, 0ull};

#pragma unroll
        for (int p = 0; p < NP; p++) {
            const u64 tpp = tp[p];
            u64 d1 = fma2(fma2(dqa[0], tpp, dqb[0]), tpp, dqc[0]);
            u64 d2 = fma2(fma2(dqa[1], tpp, dqb[1]), tpp, dqc[1]);
            u64 d3 = fma2(fma2(dqa[2], tpp, dqb[2]), tpp, dqc[2]);
            float d1l, d1h, d2l, d2h, d3l, d3h;
            up2(d1, d1l, d1h); up2(d2, d2l, d2h); up2(d3, d3l, d3h);
            u64 e1 = pk2(ex2f(d1l), ex2f(d1h));
            u64 e2 = pk2(ex2f(d2l), ex2f(d2h));
            u64 e3 = pk2(ex2f(d3l), ex2f(d3h));
            u64 sm2 = add2(add2(e1, e2), add2(e3, one2));
            float sl, sh; up2(sm2, sl, sh);
            // paired reciprocal: one MUFU for both halves
            float rr2 = rcpf(sl * sh);
            u64 rs2 = pk2(rr2 * sh, rr2 * sl);
            u64 ws2 = mul2(wsh[p][lane], rs2);

            if (last) {
                u64 g1 = mul2(e1, rs2), g2 = mul2(e2, rs2), g3 = mul2(e3, rs2);
                float rl, rh, g1l, g1h, g2l, g2h, g3l, g3h;
                up2(rs2, rl, rh); up2(g1, g1l, g1h); up2(g2, g2l, g2h); up2(g3, g3l, g3h);
                const int j = p >> 1, c = p & 1;
                const int pos = (lane + 32 * j) * 4 + 2 * c;
                gout[pos]     = make_float4(rl, g1l, g2l, g3l);
                gout[pos + 1] = make_float4(rh, g1h, g2h, g3h);
            }

            u64 f1 = mul2(e1, ws2);
            u64 f2 = mul2(e2, ws2);
            u64 t0 = mul2(ws2, tpp), t1 = mul2(f1, tpp), t2 = mul2(f2, tpp);
            A0[0] = add2(A0[0], ws2); A0[1] = add2(A0[1], f1); A0[2] = add2(A0[2], f2);
            A1[0] = add2(A1[0], t0);  A1[1] = add2(A1[1], t1); A1[2] = add2(A1[2], t2);
            A2[0] = fma2(t0, tpp, A2[0]); A2[1] = fma2(t1, tpp, A2[1]); A2[2] = fma2(t2, tpp, A2[2]);
        }

        // ---- intra-warp reduce 9 moments; k=3 via conserved totals ----
        float S00 = rsum2(A0[0]), S01 = rsum2(A0[1]), S02 = rsum2(A0[2]);
        float S10 = rsum2(A1[0]), S11 = rsum2(A1[1]), S12 = rsum2(A1[2]);
        float S20 = rsum2(A2[0]), S21 = rsum2(A2[1]), S22 = rsum2(A2[2]);

        float S0k = (k == 0) ? S00 : (k == 1) ? S01 : (k == 2) ? S02 : (W0 - S00 - S01 - S02);
        float S1k = (k == 0) ? S10 : (k == 1) ? S11 : (k == 2) ? S12 : (W1 - S10 - S11 - S12);
        float S2k = (k == 0) ? S20 : (k == 1) ? S21 : (k == 2) ? S22 : (W2 - S20 - S21 - S22);

        // ---- m-step: lane computes its k ----
        float sg = fmaxf(S0k, EPSF);
        float pv = sg + prior_p;
        float psum = pv;
        psum += __shfl_xor_sync(0xffffffffu, psum, 1);
        psum += __shfl_xor_sync(0xffffffffu, psum, 2);
        pkn = pv * rcpf(psum);
        float rsg = rcpf(sg);
        al_ = blender * S1k * rsg;                                  // a - mean
        float dv = fmaf(al_, fmaf(al_, S0k, -2.f * S1k), S2k) * rsg;
        bb = sqrtf(fmaf(dv, blender, fmaf(prior_var, omb, EPSF)));
        ib = rcpf(bb + EPSF);
        qa = NHALF_LOG2E * ib * ib;
        qb = -2.f * qa * al_;
        qc = fmaf(qa * al_, al_, __log2f((pkn + EPSF) * ib));
        make_deltas(qa, qb, qc, dqa, dqb, dqc);
    }

    // ---- tail outputs: p, a, b (lane < 4 holds k = lane) ----
    if (lane < Kc) {
        size_t base = (size_t)Bn * Ln * Kc;
        out[base + (size_t)row * Kc + lane]                       = pkn;
        out[base + (size_t)Bn * Kc + (size_t)row * Kc + lane]     = al_ + mean;
        out[base + 2 * (size_t)Bn * Kc + (size_t)row * Kc + lane] = bb;
    }
}

extern "C" void kernel_launch(void* const* d_in, const int* in_sizes, int n_in,
                              void* d_out, int out_size) {
    (void)in_sizes; (void)n_in; (void)out_size;
    em_kernel<<<Bn / RPB, TPB>>>((const float*)d_in[0], (const float*)d_in[1],
                                 (const float*)d_in[2], (const float*)d_in[3],
                                 (const float*)d_in[4], (const float*)d_in[5],
                                 (const float*)d_in[6], (const float*)d_in[7],
                                 (float*)d_out);
}